// round 1
// baseline (speedup 1.0000x reference)
#include <cuda_runtime.h>

#define NN  100000
#define EE  3200000
#define FIN 256
#define HID 16
#define NC  10

// ---------------- device scratch (no allocations allowed) ----------------
__device__ int   g_is64;
__device__ int   g_deg[NN];
__device__ float g_dinv[NN];
__device__ int   g_off[NN + 1];
__device__ int   g_cur[NN];
__device__ int   g_src[EE];
__device__ float g_g1[(size_t)NN * HID];
__device__ float g_g2[(size_t)NN * NC];

// ---------------- dtype detection: int64 vs int32 edge_index ----------------
// Values are in [0, 100000). If int64 little-endian, every high 32-bit word is 0.
// If int32, the "high word" slots are random edge values (~never all zero over 64).
__global__ void k_detect(const unsigned* __restrict__ ei) {
    int is64 = 1;
    for (int i = 0; i < 64; i++) {
        if (ei[2 * i + 1] != 0u) { is64 = 0; break; }
    }
    g_is64 = is64;
}

__global__ void k_init_deg(int n) {
    int v = blockIdx.x * blockDim.x + threadIdx.x;
    if (v < n) g_deg[v] = 1;  // self loop
}

__global__ void k_deg(const void* __restrict__ ei, int e) {
    int i = blockIdx.x * blockDim.x + threadIdx.x;
    if (i >= e) return;
    int is64 = g_is64;
    int c = is64 ? (int)((const long long*)ei)[(long long)e + i]
                 : ((const int*)ei)[e + i];
    atomicAdd(&g_deg[c], 1);
}

__global__ void k_dinv(int n) {
    int v = blockIdx.x * blockDim.x + threadIdx.x;
    if (v < n) g_dinv[v] = rsqrtf((float)g_deg[v]);
}

// Single-block exclusive scan of in-degrees (deg-1) -> CSR offsets + cursors.
__global__ void __launch_bounds__(1024) k_scan(int n, int e) {
    __shared__ int ssum[1024];
    int t = threadIdx.x;
    int per = (n + 1023) / 1024;
    int start = t * per;
    int end = min(start + per, n);
    int s = 0;
    for (int i = start; i < end; i++) s += g_deg[i] - 1;
    ssum[t] = s;
    __syncthreads();
    for (int d = 1; d < 1024; d <<= 1) {
        int v = (t >= d) ? ssum[t - d] : 0;
        __syncthreads();
        ssum[t] += v;
        __syncthreads();
    }
    int run = (t == 0) ? 0 : ssum[t - 1];
    for (int i = start; i < end; i++) {
        g_off[i] = run;
        g_cur[i] = run;
        run += g_deg[i] - 1;
    }
    if (t == 0) g_off[n] = e;
}

__global__ void k_scatter(const void* __restrict__ ei, int e) {
    int i = blockIdx.x * blockDim.x + threadIdx.x;
    if (i >= e) return;
    int is64 = g_is64;
    int r, c;
    if (is64) {
        const long long* p = (const long long*)ei;
        r = (int)p[i];
        c = (int)p[(long long)e + i];
    } else {
        const int* p = (const int*)ei;
        r = p[i];
        c = p[e + i];
    }
    int pos = atomicAdd(&g_cur[c], 1);
    g_src[pos] = r;
}

// ---------------- GEMM1: g1[v] = dinv[v] * (x[v] @ W1) ----------------
// 256 threads/block, 256 rows/tile, k streamed in 16-wide chunks through
// padded smem (pad 17 -> conflict-free LDS), W1 broadcast via LDS.128,
// double-buffered global prefetch into registers.
__global__ void __launch_bounds__(256) k_gemm1(const float4* __restrict__ x4,
                                               const float4* __restrict__ W14,
                                               int n) {
    __shared__ float4 sW[FIN * HID / 4];   // 16 KB, sW[k*4 + q] = W1[k][4q..4q+3]
    __shared__ float  sx[256 * 17];        // 17 KB chunk buffer

    int t = threadIdx.x;
    for (int i = t; i < FIN * HID / 4; i += 256) sW[i] = W14[i];

    int tile = blockIdx.x * 256;
    int rbase = t >> 2, kq = t & 3;

    float acc[16];
#pragma unroll
    for (int j = 0; j < 16; j++) acc[j] = 0.f;

    float4 pf[4];
#pragma unroll
    for (int q = 0; q < 4; q++) {
        int rg = tile + q * 64 + rbase;
        if (rg >= n) rg = n - 1;
        pf[q] = x4[(long long)rg * 64 + kq];
    }

#pragma unroll 1
    for (int c = 0; c < 16; c++) {
        __syncthreads();
#pragma unroll
        for (int q = 0; q < 4; q++) {
            int rl = q * 64 + rbase;
            float* d = &sx[rl * 17 + kq * 4];
            d[0] = pf[q].x; d[1] = pf[q].y; d[2] = pf[q].z; d[3] = pf[q].w;
        }
        __syncthreads();
        if (c < 15) {
#pragma unroll
            for (int q = 0; q < 4; q++) {
                int rg = tile + q * 64 + rbase;
                if (rg >= n) rg = n - 1;
                pf[q] = x4[(long long)rg * 64 + (c + 1) * 4 + kq];
            }
        }
#pragma unroll
        for (int kk = 0; kk < 16; kk++) {
            float xv = sx[t * 17 + kk];
            int k = c * 16 + kk;
            float4 w0 = sW[k * 4 + 0];
            float4 w1 = sW[k * 4 + 1];
            float4 w2 = sW[k * 4 + 2];
            float4 w3 = sW[k * 4 + 3];
            acc[0]  += xv * w0.x;  acc[1]  += xv * w0.y;
            acc[2]  += xv * w0.z;  acc[3]  += xv * w0.w;
            acc[4]  += xv * w1.x;  acc[5]  += xv * w1.y;
            acc[6]  += xv * w1.z;  acc[7]  += xv * w1.w;
            acc[8]  += xv * w2.x;  acc[9]  += xv * w2.y;
            acc[10] += xv * w2.z;  acc[11] += xv * w2.w;
            acc[12] += xv * w3.x;  acc[13] += xv * w3.y;
            acc[14] += xv * w3.z;  acc[15] += xv * w3.w;
        }
    }

    int v = tile + t;
    if (v < n) {
        float dv = g_dinv[v];
        float4* o = (float4*)&g_g1[(long long)v * HID];
#pragma unroll
        for (int q = 0; q < 4; q++)
            o[q] = make_float4(dv * acc[4 * q], dv * acc[4 * q + 1],
                               dv * acc[4 * q + 2], dv * acc[4 * q + 3]);
    }
}

// ---------------- Agg layer 1 fused with ReLU + GEMM2 ----------------
// warp per node; lane = e2*16 + j; out: g2[v] = dinv[v] * (relu(...) @ W2)
__global__ void __launch_bounds__(256) k_agg1(const float* __restrict__ b1,
                                              const float* __restrict__ W2,
                                              int n) {
    __shared__ float sW2[HID * NC];
    __shared__ float sb1[HID];
    int t = threadIdx.x;
    if (t < HID * NC) sW2[t] = W2[t];
    if (t < HID) sb1[t] = b1[t];
    __syncthreads();

    int warp = t >> 5, lane = t & 31;
    int v = blockIdx.x * 8 + warp;
    if (v >= n) return;

    int j = lane & 15;
    int off0 = g_off[v], off1 = g_off[v + 1];
    float acc = (lane < 16) ? g_g1[(long long)v * HID + j] : 0.0f;  // self loop
    for (int i = off0 + (lane >> 4); i < off1; i += 2) {
        int s = g_src[i];
        acc += g_g1[(long long)s * HID + j];
    }
    acc += __shfl_xor_sync(0xffffffffu, acc, 16);

    float dv = g_dinv[v];
    float t1 = fmaxf(dv * acc + sb1[j], 0.0f);  // out1 = relu(agg + b1)

    int l = (lane < NC) ? lane : 0;
    float h2 = 0.0f;
#pragma unroll
    for (int jj = 0; jj < HID; jj++) {
        float tj = __shfl_sync(0xffffffffu, t1, jj);
        h2 += tj * sW2[jj * NC + l];
    }
    if (lane < NC) g_g2[(long long)v * NC + lane] = dv * h2;
}

// ---------------- Agg layer 2 + bias + log_softmax ----------------
// warp per node; lanes 0..29 as (e3, j), 3 edges per iteration.
__global__ void __launch_bounds__(256) k_agg2(const float* __restrict__ b2,
                                              float* __restrict__ out, int n) {
    int t = threadIdx.x;
    int warp = t >> 5, lane = t & 31;
    int v = blockIdx.x * 8 + warp;
    if (v >= n) return;

    int j = lane % 10;
    int e3 = lane / 10;
    int off0 = g_off[v], off1 = g_off[v + 1];
    float acc = (lane < 10) ? g_g2[(long long)v * NC + j] : 0.0f;  // self loop
    if (lane < 30) {
        for (int i = off0 + e3; i < off1; i += 3)
            acc += g_g2[(long long)g_src[i] * NC + j];
    }
    float a1 = __shfl_down_sync(0xffffffffu, acc, 10);
    float a2 = __shfl_down_sync(0xffffffffu, acc, 20);

    float logit = 0.0f;
    if (lane < 10) logit = g_dinv[v] * (acc + a1 + a2) + __ldg(&b2[j]);

    float m = (lane < 10) ? logit : -1e30f;
#pragma unroll
    for (int d = 16; d >= 1; d >>= 1)
        m = fmaxf(m, __shfl_xor_sync(0xffffffffu, m, d));
    float s = (lane < 10) ? expf(logit - m) : 0.0f;
#pragma unroll
    for (int d = 16; d >= 1; d >>= 1)
        s += __shfl_xor_sync(0xffffffffu, s, d);

    if (lane < 10) out[(long long)v * NC + j] = logit - m - logf(s);
}

// ---------------- launch ----------------
extern "C" void kernel_launch(void* const* d_in, const int* in_sizes, int n_in,
                              void* d_out, int out_size) {
    const float* x  = (const float*)d_in[0];
    const void*  ei = d_in[1];
    const float* W1 = (const float*)d_in[2];
    const float* b1 = (const float*)d_in[3];
    const float* W2 = (const float*)d_in[4];
    const float* b2 = (const float*)d_in[5];
    float* out = (float*)d_out;

    int N = in_sizes[0] / FIN;   // 100000
    int E = in_sizes[1] / 2;     // 3200000 (element count is 2E for both dtypes)

    int nb = (N + 255) / 256;
    int eb = (E + 255) / 256;

    k_detect<<<1, 1>>>((const unsigned*)ei);
    k_init_deg<<<nb, 256>>>(N);
    k_deg<<<eb, 256>>>(ei, E);
    k_dinv<<<nb, 256>>>(N);
    k_scan<<<1, 1024>>>(N, E);
    k_scatter<<<eb, 256>>>(ei, E);
    k_gemm1<<<nb, 256>>>((const float4*)x, (const float4*)W1, N);
    k_agg1<<<(N + 7) / 8, 256>>>(b1, W2, N);
    k_agg2<<<(N + 7) / 8, 256>>>(b2, out, N);
}

// round 3
// speedup vs baseline: 1.6143x; 1.6143x over previous
#include <cuda_runtime.h>

#define NN  100000
#define EE  3200000
#define FIN 256
#define HID 16
#define NC  10
#define SCAN_T 1024

// ---------------- device scratch (no allocations allowed) ----------------
__device__ int   g_is64;
__device__ int   g_deg[NN];
__device__ float g_dinv[NN];
__device__ int   g_off[NN + 1];
__device__ int   g_cur[NN];
__device__ int   g_src[EE];
__device__ int   g_part[128];
__device__ float g_g1[(size_t)NN * HID];
__device__ float g_g2[(size_t)NN * NC];

// ---------------- pre: zero degree array + dtype detect ----------------
// int64 little-endian with values < 100000 => every high word is 0.
__global__ void k_pre(const unsigned* __restrict__ ei, int n) {
    int i = blockIdx.x * SCAN_T + threadIdx.x;
    if (i < n) g_deg[i] = 0;
    if (blockIdx.x == 0 && threadIdx.x == 0) {
        int is64 = 1;
        for (int k = 0; k < 64; k++)
            if (ei[2 * k + 1] != 0u) { is64 = 0; break; }
        g_is64 = is64;
    }
}

// ---------------- fused GEMM1 + degree count ----------------
// Blocks [0, ngb): g1[v] = x[v] @ W1 (unscaled; dinv applied per-edge later).
// Blocks [ngb, ngb+ndb): in-degree count, 4 edges/thread, vectorized loads.
__global__ void __launch_bounds__(256) k_gemm_deg(
    const float4* __restrict__ x4, const float4* __restrict__ W14,
    const void* __restrict__ ei, int n, int e, int ngb) {
    __shared__ float4 sW[FIN * HID / 4];
    __shared__ float  sx[256 * 17];

    if (blockIdx.x < ngb) {
        int t = threadIdx.x;
        for (int i = t; i < FIN * HID / 4; i += 256) sW[i] = W14[i];

        int tile = blockIdx.x * 256;
        int rbase = t >> 2, kq = t & 3;

        float acc[16];
#pragma unroll
        for (int j = 0; j < 16; j++) acc[j] = 0.f;

        float4 pf[4];
#pragma unroll
        for (int q = 0; q < 4; q++) {
            int rg = tile + q * 64 + rbase;
            if (rg >= n) rg = n - 1;
            pf[q] = x4[(long long)rg * 64 + kq];
        }

#pragma unroll 1
        for (int c = 0; c < 16; c++) {
            __syncthreads();
#pragma unroll
            for (int q = 0; q < 4; q++) {
                int rl = q * 64 + rbase;
                float* d = &sx[rl * 17 + kq * 4];
                d[0] = pf[q].x; d[1] = pf[q].y; d[2] = pf[q].z; d[3] = pf[q].w;
            }
            __syncthreads();
            if (c < 15) {
#pragma unroll
                for (int q = 0; q < 4; q++) {
                    int rg = tile + q * 64 + rbase;
                    if (rg >= n) rg = n - 1;
                    pf[q] = x4[(long long)rg * 64 + (c + 1) * 4 + kq];
                }
            }
#pragma unroll
            for (int kk = 0; kk < 16; kk++) {
                float xv = sx[t * 17 + kk];
                int k = c * 16 + kk;
                float4 w0 = sW[k * 4 + 0];
                float4 w1 = sW[k * 4 + 1];
                float4 w2 = sW[k * 4 + 2];
                float4 w3 = sW[k * 4 + 3];
                acc[0]  += xv * w0.x;  acc[1]  += xv * w0.y;
                acc[2]  += xv * w0.z;  acc[3]  += xv * w0.w;
                acc[4]  += xv * w1.x;  acc[5]  += xv * w1.y;
                acc[6]  += xv * w1.z;  acc[7]  += xv * w1.w;
                acc[8]  += xv * w2.x;  acc[9]  += xv * w2.y;
                acc[10] += xv * w2.z;  acc[11] += xv * w2.w;
                acc[12] += xv * w3.x;  acc[13] += xv * w3.y;
                acc[14] += xv * w3.z;  acc[15] += xv * w3.w;
            }
        }

        int v = tile + t;
        if (v < n) {
            float4* o = (float4*)&g_g1[(long long)v * HID];
#pragma unroll
            for (int q = 0; q < 4; q++)
                o[q] = make_float4(acc[4 * q], acc[4 * q + 1],
                                   acc[4 * q + 2], acc[4 * q + 3]);
        }
    } else {
        int i0 = ((blockIdx.x - ngb) * 256 + threadIdx.x) * 4;
        if (i0 >= e) return;
        int is64 = g_is64;
        int c[4];
        if (i0 + 3 < e) {
            if (is64) {
                const longlong2* cp =
                    (const longlong2*)((const long long*)ei + e);
                longlong2 a = cp[i0 >> 1];
                longlong2 b = cp[(i0 >> 1) + 1];
                c[0] = (int)a.x; c[1] = (int)a.y; c[2] = (int)b.x; c[3] = (int)b.y;
            } else {
                int4 q = ((const int4*)((const int*)ei + e))[i0 >> 2];
                c[0] = q.x; c[1] = q.y; c[2] = q.z; c[3] = q.w;
            }
            atomicAdd(&g_deg[c[0]], 1);
            atomicAdd(&g_deg[c[1]], 1);
            atomicAdd(&g_deg[c[2]], 1);
            atomicAdd(&g_deg[c[3]], 1);
        } else {
            for (int k = 0; k < 4 && i0 + k < e; k++) {
                int cc = is64 ? (int)((const long long*)ei)[(long long)e + i0 + k]
                              : ((const int*)ei)[e + i0 + k];
                atomicAdd(&g_deg[cc], 1);
            }
        }
    }
}

// ---------------- multi-block scan of in-degrees ----------------
__global__ void __launch_bounds__(SCAN_T) k_scan1(int n) {
    __shared__ int ss[SCAN_T];
    int t = threadIdx.x;
    int i = blockIdx.x * SCAN_T + t;
    int d = (i < n) ? g_deg[i] : 0;
    if (i < n) g_dinv[i] = rsqrtf((float)(d + 1));  // +1 self loop
    ss[t] = d;
    __syncthreads();
    for (int o = 1; o < SCAN_T; o <<= 1) {
        int v = (t >= o) ? ss[t - o] : 0;
        __syncthreads();
        ss[t] += v;
        __syncthreads();
    }
    if (i < n) g_off[i] = ss[t] - d;  // local exclusive
    if (t == SCAN_T - 1) g_part[blockIdx.x] = ss[t];
}

__global__ void __launch_bounds__(128) k_scan2(int nb) {
    __shared__ int ss[128];
    int t = threadIdx.x;
    int v = (t < nb) ? g_part[t] : 0;
    ss[t] = v;
    __syncthreads();
    for (int o = 1; o < 128; o <<= 1) {
        int u = (t >= o) ? ss[t - o] : 0;
        __syncthreads();
        ss[t] += u;
        __syncthreads();
    }
    g_part[t] = ss[t] - v;  // exclusive
}

__global__ void __launch_bounds__(SCAN_T) k_scan3(int n, int e) {
    int i = blockIdx.x * SCAN_T + threadIdx.x;
    if (i < n) {
        int o = g_off[i] + g_part[i >> 10];
        g_off[i] = o;
        g_cur[i] = o;
    }
    if (blockIdx.x == 0 && threadIdx.x == 0) g_off[n] = e;
}

// ---------------- scatter: build CSR src list (4 edges/thread) ----------------
__global__ void __launch_bounds__(256) k_scatter(const void* __restrict__ ei, int e) {
    int i0 = (blockIdx.x * 256 + threadIdx.x) * 4;
    if (i0 >= e) return;
    int is64 = g_is64;
    if (i0 + 3 < e) {
        int r[4], c[4];
        if (is64) {
            const longlong2* rp = (const longlong2*)ei;
            const longlong2* cp = (const longlong2*)((const long long*)ei + e);
            longlong2 ra = rp[i0 >> 1], rb = rp[(i0 >> 1) + 1];
            longlong2 ca = cp[i0 >> 1], cb = cp[(i0 >> 1) + 1];
            r[0] = (int)ra.x; r[1] = (int)ra.y; r[2] = (int)rb.x; r[3] = (int)rb.y;
            c[0] = (int)ca.x; c[1] = (int)ca.y; c[2] = (int)cb.x; c[3] = (int)cb.y;
        } else {
            int4 rq = ((const int4*)ei)[i0 >> 2];
            int4 cq = ((const int4*)((const int*)ei + e))[i0 >> 2];
            r[0] = rq.x; r[1] = rq.y; r[2] = rq.z; r[3] = rq.w;
            c[0] = cq.x; c[1] = cq.y; c[2] = cq.z; c[3] = cq.w;
        }
#pragma unroll
        for (int k = 0; k < 4; k++) {
            int pos = atomicAdd(&g_cur[c[k]], 1);
            g_src[pos] = r[k];
        }
    } else {
        for (int k = 0; k < 4 && i0 + k < e; k++) {
            int r, c;
            if (is64) {
                const long long* p = (const long long*)ei;
                r = (int)p[i0 + k];
                c = (int)p[(long long)e + i0 + k];
            } else {
                const int* p = (const int*)ei;
                r = p[i0 + k];
                c = p[e + i0 + k];
            }
            int pos = atomicAdd(&g_cur[c], 1);
            g_src[pos] = r;
        }
    }
}

// ---------------- Agg layer 1 (+bias, ReLU) fused with GEMM2 ----------------
// Warp per node. Batch-load 32 src indices + their dinv coalesced, then
// shfl-broadcast gather with full unroll (2 edges per step, MLP ~16).
// All shuffles executed unconditionally by all 32 lanes.
__global__ void __launch_bounds__(256) k_agg1(const float* __restrict__ b1,
                                              const float* __restrict__ W2,
                                              int n) {
    __shared__ float sW2[HID * NC];
    __shared__ float sb1[HID];
    int t = threadIdx.x;
    if (t < HID * NC) sW2[t] = W2[t];
    if (t < HID) sb1[t] = b1[t];
    __syncthreads();

    int warp = t >> 5, lane = t & 31;
    int v = blockIdx.x * 8 + warp;
    if (v >= n) return;

    int j = lane & 15, half = lane >> 4;
    int off0 = g_off[v], off1 = g_off[v + 1];
    float dv = g_dinv[v];
    // self loop term: dinv[v] * g1[v][j], counted once (half 0 only)
    float acc = (half == 0) ? dv * g_g1[(size_t)v * HID + j] : 0.0f;

    for (int base = off0; base < off1; base += 32) {
        int i = base + lane;
        int sreg = -1;
        float dreg = 0.0f;
        if (i < off1) {
            sreg = g_src[i];
            dreg = g_dinv[sreg];
        }
#pragma unroll
        for (int k = 0; k < 32; k += 2) {
            int   ss = __shfl_sync(0xffffffffu, sreg, k + half);
            float dd = __shfl_sync(0xffffffffu, dreg, k + half);
            if (ss >= 0) acc += dd * g_g1[(size_t)ss * HID + j];
        }
    }
    acc += __shfl_xor_sync(0xffffffffu, acc, 16);

    float t1 = fmaxf(fmaf(dv, acc, sb1[j]), 0.0f);  // relu(dv*agg + b1)

    int l = (lane < NC) ? lane : 0;
    float h2 = 0.0f;
#pragma unroll
    for (int jj = 0; jj < HID; jj++) {
        float tj = __shfl_sync(0xffffffffu, t1, jj);
        h2 += tj * sW2[jj * NC + l];
    }
    if (lane < NC) g_g2[(size_t)v * NC + lane] = dv * h2;
}

// ---------------- Agg layer 2 + bias + log_softmax ----------------
// Warp per node; batched coalesced src loads + shfl broadcast, 3 edges/step.
// FIX vs R2: shuffles are hoisted out of the divergent guard — all 32 lanes
// execute every __shfl_sync with a clamped source lane; only the accumulate
// is predicated. (The R2 version shuffled inside `if(e3<3 && idx<32)`, which
// is UB and produced garbage indices -> OOB gather -> illegal access.)
__global__ void __launch_bounds__(256) k_agg2(const float* __restrict__ b2,
                                              float* __restrict__ out, int n) {
    int t = threadIdx.x;
    int warp = t >> 5, lane = t & 31;
    int v = blockIdx.x * 8 + warp;
    if (v >= n) return;

    int j = lane % 10;
    int e3 = lane / 10;  // 0..2 active; 3 for lanes 30/31 (gather-idle)
    int off0 = g_off[v], off1 = g_off[v + 1];
    float acc = (lane < 10) ? g_g2[(size_t)v * NC + j] : 0.0f;  // self loop

    for (int base = off0; base < off1; base += 32) {
        int i = base + lane;
        int sreg = (i < off1) ? g_src[i] : -1;
#pragma unroll
        for (int kk = 0; kk < 11; kk++) {
            int idx = kk * 3 + e3;                  // 0..35
            int src_lane = idx & 31;                // clamp for safety
            int ss = __shfl_sync(0xffffffffu, sreg, src_lane);  // all lanes
            if (e3 < 3 && idx < 32 && ss >= 0)
                acc += g_g2[(size_t)ss * NC + j];
        }
    }
    float a1 = __shfl_down_sync(0xffffffffu, acc, 10);
    float a2 = __shfl_down_sync(0xffffffffu, acc, 20);

    float logit = 0.0f;
    if (lane < 10) logit = g_dinv[v] * (acc + a1 + a2) + __ldg(&b2[j]);

    float m = (lane < 10) ? logit : -1e30f;
#pragma unroll
    for (int d = 16; d >= 1; d >>= 1)
        m = fmaxf(m, __shfl_xor_sync(0xffffffffu, m, d));
    float s = (lane < 10) ? expf(logit - m) : 0.0f;
#pragma unroll
    for (int d = 16; d >= 1; d >>= 1)
        s += __shfl_xor_sync(0xffffffffu, s, d);

    if (lane < 10) out[(size_t)v * NC + j] = logit - m - logf(s);
}

// ---------------- launch ----------------
extern "C" void kernel_launch(void* const* d_in, const int* in_sizes, int n_in,
                              void* d_out, int out_size) {
    const float* x  = (const float*)d_in[0];
    const void*  ei = d_in[1];
    const float* W1 = (const float*)d_in[2];
    const float* b1 = (const float*)d_in[3];
    const float* W2 = (const float*)d_in[4];
    const float* b2 = (const float*)d_in[5];
    float* out = (float*)d_out;

    int N = in_sizes[0] / FIN;   // 100000
    int E = in_sizes[1] / 2;     // 3200000

    int ngb = (N + 255) / 256;           // gemm blocks
    int ndb = (E + 1023) / 1024;         // degree blocks (4 edges/thread)
    int nsb = (N + SCAN_T - 1) / SCAN_T; // scan blocks

    k_pre<<<nsb, SCAN_T>>>((const unsigned*)ei, N);
    k_gemm_deg<<<ngb + ndb, 256>>>((const float4*)x, (const float4*)W1, ei, N, E, ngb);
    k_scan1<<<nsb, SCAN_T>>>(N);
    k_scan2<<<1, 128>>>(nsb);
    k_scan3<<<nsb, SCAN_T>>>(N, E);
    k_scatter<<<(E + 1023) / 1024, 256>>>(ei, E);
    k_agg1<<<(N + 7) / 8, 256>>>(b1, W2, N);
    k_agg2<<<(N + 7) / 8, 256>>>(b2, out, N);
}